// round 13
// baseline (speedup 1.0000x reference)
#include <cuda_runtime.h>
#include <cuda_fp16.h>
#include <cstdint>
#include <cstddef>

#define T_STEPS 512
#define B_SZ    128
#define E_SEQ   768
#define COND    256
#define H_DIM   1024
#define KSEQ    768
#define G3      3072
#define M_TOT   (T_STEPS * B_SZ)
#define NBLK    128
#define NHELP   20
#define TSPLIT  448                               // rec steps [TSPLIT,512) produced by helpers
#define NTILES  ((T_STEPS - TSPLIT) * 24)         // 1536 helper gx tiles

// ---------------- static device scratch --------------------------------------
__device__ float   g_gx[(size_t)M_TOT * G3];
__device__ float   g_gw[(size_t)B_SZ * G3];
__device__ __half  g_whh[(size_t)G3 * H_DIM];
__device__ __half  g_wih[(size_t)G3 * KSEQ];
__device__ __half  g_xh[(size_t)M_TOT * KSEQ];
__device__ __half  g_hf[2][B_SZ * H_DIM];
__device__ unsigned g_count;
__device__ unsigned g_hprog[NHELP];               // per-helper completed-tile count

// ---------------- fused prep kernels (persist stays launch #4) ----------------
__global__ __launch_bounds__(256) void k_prep1(const float* __restrict__ whh,
                                               const float* __restrict__ word,
                                               const float* __restrict__ wih) {
    __shared__ float wrow[COND];
    const int tid = threadIdx.x;
    if (blockIdx.x < 12288) {
        int i = blockIdx.x * 256 + tid;
        g_whh[i] = __float2half(whh[i]);
        return;
    }
    const int b = blockIdx.x - 12288;
    if (b == 0) {
        if (tid == 0) g_count = 0u;
        if (tid < NHELP) g_hprog[tid] = 0u;
    }
    if (tid < COND) wrow[tid] = word[b * COND + tid];
    __syncthreads();
    for (int j = tid; j < G3; j += 256) {
        const float4* wr = (const float4*)&wih[(size_t)j * (COND + KSEQ)];
        float s = 0.0f;
        #pragma unroll 8
        for (int k = 0; k < COND / 4; k++) {
            float4 wv = wr[k];
            s += wv.x * wrow[4*k] + wv.y * wrow[4*k+1] + wv.z * wrow[4*k+2] + wv.w * wrow[4*k+3];
        }
        g_gw[(size_t)b * G3 + j] = s;
    }
}
__global__ __launch_bounds__(256) void k_prep2(const float* __restrict__ wih,
                                               const float* __restrict__ seq) {
    const int tid = threadIdx.x;
    if (blockIdx.x < 9216) {
        int i = blockIdx.x * 256 + tid;
        int j = i / KSEQ, k = i - j * KSEQ;
        g_wih[i] = __float2half(wih[(size_t)j * (COND + KSEQ) + COND + k]);
        return;
    }
    size_t i = (size_t)(blockIdx.x - 9216) * 256 + tid;
    if (i >= (size_t)M_TOT * KSEQ / 4) return;
    float4 v = ((const float4*)seq)[i];
    __half2 p0 = {__float2half(v.x), __float2half(v.y)};
    __half2 p1 = {__float2half(v.z), __float2half(v.w)};
    ((__half2*)g_xh)[2 * i]     = p0;
    ((__half2*)g_xh)[2 * i + 1] = p1;
}

// ---------------- PTX helpers --------------------------------------------------
__device__ __forceinline__ unsigned smem_u32(const void* p) {
    return (unsigned)__cvta_generic_to_shared(p);
}
__device__ __forceinline__ void cp16(unsigned dst, const void* src) {
    asm volatile("cp.async.cg.shared.global [%0], [%1], 16;\n" :: "r"(dst), "l"(src));
}
#define CP_COMMIT()  asm volatile("cp.async.commit_group;\n")
#define CP_WAIT(n)   asm volatile("cp.async.wait_group %0;\n" :: "n"(n))

__device__ __forceinline__ void ldm4(unsigned r[4], unsigned addr) {
    asm volatile("ldmatrix.sync.aligned.m8n8.x4.shared.b16 {%0,%1,%2,%3}, [%4];"
        : "=r"(r[0]), "=r"(r[1]), "=r"(r[2]), "=r"(r[3]) : "r"(addr));
}
__device__ __forceinline__ void mmaf16(float c[4], unsigned a0, unsigned a1,
                                       unsigned a2, unsigned a3,
                                       unsigned b0, unsigned b1) {
    asm volatile(
        "mma.sync.aligned.m16n8k16.row.col.f32.f16.f16.f32 "
        "{%0,%1,%2,%3},{%4,%5,%6,%7},{%8,%9},{%0,%1,%2,%3};\n"
        : "+f"(c[0]), "+f"(c[1]), "+f"(c[2]), "+f"(c[3])
        : "r"(a0), "r"(a1), "r"(a2), "r"(a3), "r"(b0), "r"(b1));
}

// ---------------- gx tile body (shared by gx kernel and helpers) ---------------
#define ROWB    144
#define TILEB   (128 * ROWB)
#define STAGEB  (2 * TILEB)
#define GXS_SMEM (2 * STAGEB)

__device__ __forceinline__ void gx_tile(unsigned dynb, int n0, int m0, int tid) {
    const int wid = tid >> 5, lid = tid & 31;
    const int wm = wid & 3, wn = wid >> 2;

    float acc[2][8][4];
    #pragma unroll
    for (int mt = 0; mt < 2; mt++)
        #pragma unroll
        for (int nt = 0; nt < 8; nt++)
            #pragma unroll
            for (int c = 0; c < 4; c++) acc[mt][nt][c] = 0.0f;

    auto load_chunk = [&](int c, int s) {
        const int k0 = c * 64;
        const unsigned sb = dynb + s * STAGEB;
        #pragma unroll
        for (int it = 0; it < 8; it++) {
            int i = tid + it * 256;
            int t = i >> 10;
            int r = (i >> 3) & 127;
            int q = i & 7;
            const __half* src = (t == 0)
                ? g_xh  + (size_t)(m0 + r) * KSEQ + k0 + q * 8
                : g_wih + (size_t)(n0 + r) * KSEQ + k0 + q * 8;
            cp16(sb + t * TILEB + r * ROWB + q * 16, src);
        }
        CP_COMMIT();
    };

    const int lrow = lid & 15;
    const int lcol = (lid >> 4) * 16;

    load_chunk(0, 0);

    for (int c = 0; c < 12; c++) {
        if (c < 11) { load_chunk(c + 1, (c + 1) & 1); CP_WAIT(1); }
        else        { CP_WAIT(0); }
        __syncthreads();

        const unsigned sb = dynb + (c & 1) * STAGEB;
        const unsigned aX = sb;
        const unsigned bW = sb + TILEB;

        #pragma unroll
        for (int k16 = 0; k16 < 4; k16++) {
            const unsigned kb = k16 * 32 + lcol;
            unsigned a[2][4], b[4][4];
            #pragma unroll
            for (int mt = 0; mt < 2; mt++)
                ldm4(a[mt], aX + (wm * 32 + mt * 16 + lrow) * ROWB + kb);
            #pragma unroll
            for (int j = 0; j < 4; j++)
                ldm4(b[j], bW + (wn * 64 + j * 16 + lrow) * ROWB + kb);
            #pragma unroll
            for (int mt = 0; mt < 2; mt++)
                #pragma unroll
                for (int j = 0; j < 4; j++) {
                    mmaf16(acc[mt][2*j],   a[mt][0], a[mt][1], a[mt][2], a[mt][3], b[j][0], b[j][2]);
                    mmaf16(acc[mt][2*j+1], a[mt][0], a[mt][1], a[mt][2], a[mt][3], b[j][1], b[j][3]);
                }
        }
        __syncthreads();
    }

    #pragma unroll
    for (int mt = 0; mt < 2; mt++) {
        int row = m0 + wm * 32 + mt * 16 + (lid >> 2);
        #pragma unroll
        for (int nt = 0; nt < 8; nt++) {
            int col = n0 + wn * 64 + nt * 8 + 2 * (lid & 3);
            float2 v0 = {acc[mt][nt][0], acc[mt][nt][1]};
            float2 v1 = {acc[mt][nt][2], acc[mt][nt][3]};
            *(float2*)&g_gx[(size_t)row * G3 + col]       = v0;
            *(float2*)&g_gx[(size_t)(row + 8) * G3 + col] = v1;
        }
    }
}

// gx kernel: only timesteps [0, TSPLIT)
__global__ __launch_bounds__(256, 2) void k_gx_mma() {
    extern __shared__ __align__(16) char dyn[];
    gx_tile(smem_u32(dyn), blockIdx.x * 128, blockIdx.y * 128, threadIdx.x);
}

// ---------------- persistent GRU recurrence + gx helpers -----------------------
#define WS_LDW 516
#define HB_ROWB 144
#define HB_BUF  (128 * HB_ROWB)
#define PERS_SMEM (24 * WS_LDW * 4 + 4 * HB_BUF)   // 123264 B (>= GXS_SMEM)

__device__ __forceinline__ void bar_arrive() {
    __syncthreads();
    if (threadIdx.x == 0)
        asm volatile("red.release.gpu.global.add.u32 [%0], 1;"
                     :: "l"(&g_count) : "memory");
}
// wait for barrier target AND (if X>0) helper gx frontier >= X
__device__ __forceinline__ void bar_wait(unsigned target, int X) {
    if (threadIdx.x == 0) {
        unsigned v;
        do {
            asm volatile("ld.acquire.gpu.global.u32 %0, [%1];"
                         : "=r"(v) : "l"(&g_count) : "memory");
        } while (v < target);
        if (X > 0) {
            int frontier;
            do {
                frontier = 0x7fffffff;
                #pragma unroll
                for (int h = 0; h < NHELP; h++) {
                    unsigned p;
                    asm volatile("ld.acquire.gpu.global.u32 %0, [%1];"
                                 : "=r"(p) : "l"(&g_hprog[h]) : "memory");
                    int f = h + NHELP * (int)p;     // smallest not-done tile of helper h
                    frontier = f < frontier ? f : frontier;
                }
            } while (frontier < X);
        }
    }
    __syncthreads();
}

__device__ __forceinline__ float sig(float x) { return 1.0f / (1.0f + __expf(-x)); }

__global__ __launch_bounds__(256) void k_gru_persist(
        const float* __restrict__ h0, const float* __restrict__ bih,
        const float* __restrict__ bhh, float* __restrict__ out, int wh)
{
    extern __shared__ __align__(16) unsigned wsm[];
    unsigned* ws = wsm;
    const unsigned wsb = smem_u32(ws);

    // ---------- helper blocks: produce gx tiles for t in [TSPLIT, 512) ----------
    if (blockIdx.x >= NBLK) {
        const int h = blockIdx.x - NBLK;
        for (int x = h; x < NTILES; x += NHELP) {
            int t  = TSPLIT + x / 24;
            int n0 = (x % 24) * 128;
            gx_tile(wsb, n0, t * 128, threadIdx.x);
            __syncthreads();
            if (threadIdx.x == 0)
                asm volatile("red.release.gpu.global.add.u32 [%0], 1;"
                             :: "l"(&g_hprog[h]) : "memory");
        }
        return;
    }

    // ---------- recurrence blocks (R10 structure, f32-acc) ----------
    const unsigned hbb = wsb + 24 * WS_LDW * 4;

    const int tid = threadIdx.x, w = tid >> 5, l = tid & 31;
    const int l4 = l & 3, n = l >> 2;
    const int j0 = blockIdx.x * 8;

    const unsigned* whh32 = (const unsigned*)g_whh;
    for (int i = tid; i < 24 * 512; i += 256) {
        int rr = i >> 9, kk = i & 511;
        int g = rr >> 3, jr = rr & 7;
        ws[rr * WS_LDW + kk] = whh32[(size_t)(g * 1024 + j0 + jr) * 512 + kk];
    }

    const int rA = w * 16 + n, rB = rA + 8;
    const int jc = j0 + l4 * 2;

    const unsigned aAddr = hbb + (unsigned)(w * 16 + (l & 15)) * HB_ROWB + (unsigned)(l >> 4) * 16;
    unsigned bAddr[3];
    #pragma unroll
    for (int g = 0; g < 3; g++)
        bAddr[g] = wsb + (unsigned)((g * 8 + (l & 7)) * WS_LDW * 4) + (unsigned)(l >> 3) * 16;

    const int srow0 = w * 16 + (l >> 3);
    const int sq16  = (l & 7) * 16;

    float biA[3][2], biB[3][2], bh[3][2];
    #pragma unroll
    for (int g = 0; g < 3; g++) {
        float b0 = bih[g * 1024 + jc], b1 = bih[g * 1024 + jc + 1];
        biA[g][0] = b0 + g_gw[(size_t)rA * G3 + g * 1024 + jc];
        biA[g][1] = b1 + g_gw[(size_t)rA * G3 + g * 1024 + jc + 1];
        biB[g][0] = b0 + g_gw[(size_t)rB * G3 + g * 1024 + jc];
        biB[g][1] = b1 + g_gw[(size_t)rB * G3 + g * 1024 + jc + 1];
        bh[g][0] = bhh[g * 1024 + jc]; bh[g][1] = bhh[g * 1024 + jc + 1];
    }

    float hA0 = h0[rA * H_DIM + jc], hA1 = h0[rA * H_DIM + jc + 1];
    float hB0 = h0[rB * H_DIM + jc], hB1 = h0[rB * H_DIM + jc + 1];

    auto wr_h = [&](unsigned* dst, int r, float v0, float v1) {
        __half2 p = {__float2half(v0), __float2half(v1)};
        __stcg(&dst[r * 512 + (jc >> 1)], *(unsigned*)&p);
    };

    float2 xA[3], xB[3];
    #pragma unroll
    for (int g = 0; g < 3; g++) {
        xA[g] = *(const float2*)&g_gx[(size_t)rA * G3 + g * 1024 + jc];
        xB[g] = *(const float2*)&g_gx[(size_t)rB * G3 + g * 1024 + jc];
    }

    wr_h((unsigned*)g_hf[0], rA, hA0, hA1);
    wr_h((unsigned*)g_hf[0], rB, hB0, hB1);
    bar_arrive();
    bar_wait(NBLK, 0);

    unsigned tgt = 2 * NBLK;
    for (int t = 0; t < T_STEPS; t++) {
        const char* hsrc = (const char*)g_hf[t & 1];
        unsigned* hnxt   = (unsigned*)g_hf[(t + 1) & 1];

        auto stage = [&](int gi) {
            if (gi < 16) {
                const unsigned db = hbb + (unsigned)(gi & 3) * HB_BUF;
                #pragma unroll
                for (int it = 0; it < 4; it++) {
                    int r = srow0 + it * 4;
                    cp16(db + (unsigned)r * HB_ROWB + sq16,
                         hsrc + (size_t)r * 2048 + gi * 128 + sq16);
                }
            }
            CP_COMMIT();
        };

        float acc[3][4];
        #pragma unroll
        for (int g = 0; g < 3; g++)
            #pragma unroll
            for (int c = 0; c < 4; c++) acc[g][c] = 0.0f;

        stage(0); stage(1); stage(2);
        #pragma unroll 1
        for (int gi = 0; gi < 16; gi++) {
            CP_WAIT(2);
            __syncwarp();
            const unsigned ab = aAddr + (unsigned)(gi & 3) * HB_BUF;
            unsigned A0[4], A1[4], A2[4], A3[4];
            ldm4(A0, ab);       ldm4(A1, ab + 32);
            ldm4(A2, ab + 64);  ldm4(A3, ab + 96);
            stage(gi + 3);
            #pragma unroll
            for (int g = 0; g < 3; g++) {
                unsigned bb[4], bb2[4];
                ldm4(bb,  bAddr[g] + gi * 128);
                ldm4(bb2, bAddr[g] + gi * 128 + 64);
                mmaf16(acc[g], A0[0], A0[1], A0[2], A0[3], bb[0],  bb[1]);
                mmaf16(acc[g], A1[0], A1[1], A1[2], A1[3], bb[2],  bb[3]);
                mmaf16(acc[g], A2[0], A2[1], A2[2], A2[3], bb2[0], bb2[1]);
                mmaf16(acc[g], A3[0], A3[1], A3[2], A3[3], bb2[2], bb2[3]);
            }
        }

        {
            float r0 = sig(xA[0].x + biA[0][0] + acc[0][0] + bh[0][0]);
            float z0 = sig(xA[1].x + biA[1][0] + acc[1][0] + bh[1][0]);
            float n0 = tanhf(xA[2].x + biA[2][0] + r0 * (acc[2][0] + bh[2][0]));
            hA0 = (1.0f - z0) * n0 + z0 * hA0;
            float r1 = sig(xA[0].y + biA[0][1] + acc[0][1] + bh[0][1]);
            float z1 = sig(xA[1].y + biA[1][1] + acc[1][1] + bh[1][1]);
            float n1 = tanhf(xA[2].y + biA[2][1] + r1 * (acc[2][1] + bh[2][1]));
            hA1 = (1.0f - z1) * n1 + z1 * hA1;
            float r2 = sig(xB[0].x + biB[0][0] + acc[0][2] + bh[0][0]);
            float z2 = sig(xB[1].x + biB[1][0] + acc[1][2] + bh[1][0]);
            float n2 = tanhf(xB[2].x + biB[2][0] + r2 * (acc[2][2] + bh[2][0]));
            hB0 = (1.0f - z2) * n2 + z2 * hB0;
            float r3 = sig(xB[0].y + biB[0][1] + acc[0][3] + bh[0][1]);
            float z3 = sig(xB[1].y + biB[1][1] + acc[1][3] + bh[1][1]);
            float n3 = tanhf(xB[2].y + biB[2][1] + r3 * (acc[2][3] + bh[2][1]));
            hB1 = (1.0f - z3) * n3 + z3 * hB1;
        }

        float2 oA = {hA0, hA1}, oB = {hB0, hB1};
        wr_h(hnxt, rA, hA0, hA1);
        wr_h(hnxt, rB, hB0, hB1);

        if (t == T_STEPS - 1) {
            *(float2*)&out[((size_t)t * B_SZ + rA) * H_DIM + jc] = oA;
            *(float2*)&out[((size_t)t * B_SZ + rB) * H_DIM + jc] = oB;
            if (wh) {
                *(float2*)&out[(size_t)M_TOT * H_DIM + (size_t)rA * H_DIM + jc] = oA;
                *(float2*)&out[(size_t)M_TOT * H_DIM + (size_t)rB * H_DIM + jc] = oB;
            }
        } else {
            bar_arrive();
            *(float2*)&out[((size_t)t * B_SZ + rA) * H_DIM + jc] = oA;
            *(float2*)&out[((size_t)t * B_SZ + rB) * H_DIM + jc] = oB;
            const float* gxn = g_gx + (size_t)(t + 1) * B_SZ * G3;
            if (t + 1 < TSPLIT) {
                // gx[t+1] precomputed: prefetch inside barrier slack
                #pragma unroll
                for (int g = 0; g < 3; g++) {
                    xA[g] = *(const float2*)&gxn[(size_t)rA * G3 + g * 1024 + jc];
                    xB[g] = *(const float2*)&gxn[(size_t)rB * G3 + g * 1024 + jc];
                }
                bar_wait(tgt, 0);
            } else {
                // helper-produced: wait for tiles of step t+1 before loading
                bar_wait(tgt, (t + 2 - TSPLIT) * 24);
                #pragma unroll
                for (int g = 0; g < 3; g++) {
                    xA[g] = *(const float2*)&gxn[(size_t)rA * G3 + g * 1024 + jc];
                    xB[g] = *(const float2*)&gxn[(size_t)rB * G3 + g * 1024 + jc];
                }
            }
            tgt += NBLK;
        }
    }
}

// ---------------- launch ------------------------------------------------------
extern "C" void kernel_launch(void* const* d_in, const int* in_sizes, int n_in,
                              void* d_out, int out_size) {
    const float* seq  = (const float*)d_in[0];
    const float* word = (const float*)d_in[1];
    const float* h0   = (const float*)d_in[2];
    const float* wih  = (const float*)d_in[3];
    const float* whh  = (const float*)d_in[4];
    const float* bih  = (const float*)d_in[5];
    const float* bhh  = (const float*)d_in[6];
    float* out = (float*)d_out;
    (void)in_sizes; (void)n_in;

    cudaFuncSetAttribute(k_gx_mma, cudaFuncAttributeMaxDynamicSharedMemorySize, GXS_SMEM);
    cudaFuncSetAttribute(k_gru_persist, cudaFuncAttributeMaxDynamicSharedMemorySize, PERS_SMEM);

    const int hidden_ok = (out_size >= T_STEPS * B_SZ * H_DIM + B_SZ * H_DIM) ? 1 : 0;

    k_prep1<<<12288 + 128, 256>>>(whh, word, wih);
    k_prep2<<<9216 + 49152, 256>>>(wih, seq);
    k_gx_mma<<<dim3(G3 / 128, TSPLIT), 256, GXS_SMEM>>>();
    k_gru_persist<<<NBLK + NHELP, 256, PERS_SMEM>>>(h0, bih, bhh, out, hidden_ok);
}

// round 14
// speedup vs baseline: 1.0695x; 1.0695x over previous
#include <cuda_runtime.h>
#include <cuda_fp16.h>
#include <cstdint>
#include <cstddef>

#define T_STEPS 512
#define B_SZ    128
#define E_SEQ   768
#define COND    256
#define H_DIM   1024
#define KSEQ    768
#define G3      3072
#define M_TOT   (T_STEPS * B_SZ)
#define NBLK    128
#define NHELP   20
#define TSPLIT  480                               // rec steps [TSPLIT,512) produced by helpers
#define NTILES  ((T_STEPS - TSPLIT) * 24)         // 768 helper gx tiles

// ---------------- static device scratch --------------------------------------
__device__ float   g_gx[(size_t)M_TOT * G3];
__device__ float   g_gw[(size_t)B_SZ * G3];
__device__ __half  g_whh[(size_t)G3 * H_DIM];
__device__ __half  g_wih[(size_t)G3 * KSEQ];
__device__ __half  g_xh[(size_t)M_TOT * KSEQ];
__device__ __half  g_hf[2][B_SZ * H_DIM];
__device__ unsigned g_count;
__device__ unsigned g_hprog[NHELP];               // per-helper completed-tile count

// ---------------- fused prep kernels (persist stays launch #4) ----------------
__global__ __launch_bounds__(256) void k_prep1(const float* __restrict__ whh,
                                               const float* __restrict__ word,
                                               const float* __restrict__ wih) {
    __shared__ float wrow[COND];
    const int tid = threadIdx.x;
    if (blockIdx.x < 12288) {
        int i = blockIdx.x * 256 + tid;
        g_whh[i] = __float2half(whh[i]);
        return;
    }
    const int b = blockIdx.x - 12288;
    if (b == 0) {
        if (tid == 0) g_count = 0u;
        if (tid < NHELP) g_hprog[tid] = 0u;
    }
    if (tid < COND) wrow[tid] = word[b * COND + tid];
    __syncthreads();
    for (int j = tid; j < G3; j += 256) {
        const float4* wr = (const float4*)&wih[(size_t)j * (COND + KSEQ)];
        float s = 0.0f;
        #pragma unroll 8
        for (int k = 0; k < COND / 4; k++) {
            float4 wv = wr[k];
            s += wv.x * wrow[4*k] + wv.y * wrow[4*k+1] + wv.z * wrow[4*k+2] + wv.w * wrow[4*k+3];
        }
        g_gw[(size_t)b * G3 + j] = s;
    }
}
__global__ __launch_bounds__(256) void k_prep2(const float* __restrict__ wih,
                                               const float* __restrict__ seq) {
    const int tid = threadIdx.x;
    if (blockIdx.x < 9216) {
        int i = blockIdx.x * 256 + tid;
        int j = i / KSEQ, k = i - j * KSEQ;
        g_wih[i] = __float2half(wih[(size_t)j * (COND + KSEQ) + COND + k]);
        return;
    }
    size_t i = (size_t)(blockIdx.x - 9216) * 256 + tid;
    if (i >= (size_t)M_TOT * KSEQ / 4) return;
    float4 v = ((const float4*)seq)[i];
    __half2 p0 = {__float2half(v.x), __float2half(v.y)};
    __half2 p1 = {__float2half(v.z), __float2half(v.w)};
    ((__half2*)g_xh)[2 * i]     = p0;
    ((__half2*)g_xh)[2 * i + 1] = p1;
}

// ---------------- PTX helpers --------------------------------------------------
__device__ __forceinline__ unsigned smem_u32(const void* p) {
    return (unsigned)__cvta_generic_to_shared(p);
}
__device__ __forceinline__ void cp16(unsigned dst, const void* src) {
    asm volatile("cp.async.cg.shared.global [%0], [%1], 16;\n" :: "r"(dst), "l"(src));
}
#define CP_COMMIT()  asm volatile("cp.async.commit_group;\n")
#define CP_WAIT(n)   asm volatile("cp.async.wait_group %0;\n" :: "n"(n))

__device__ __forceinline__ void ldm4(unsigned r[4], unsigned addr) {
    asm volatile("ldmatrix.sync.aligned.m8n8.x4.shared.b16 {%0,%1,%2,%3}, [%4];"
        : "=r"(r[0]), "=r"(r[1]), "=r"(r[2]), "=r"(r[3]) : "r"(addr));
}
__device__ __forceinline__ void mmaf16(float c[4], unsigned a0, unsigned a1,
                                       unsigned a2, unsigned a3,
                                       unsigned b0, unsigned b1) {
    asm volatile(
        "mma.sync.aligned.m16n8k16.row.col.f32.f16.f16.f32 "
        "{%0,%1,%2,%3},{%4,%5,%6,%7},{%8,%9},{%0,%1,%2,%3};\n"
        : "+f"(c[0]), "+f"(c[1]), "+f"(c[2]), "+f"(c[3])
        : "r"(a0), "r"(a1), "r"(a2), "r"(a3), "r"(b0), "r"(b1));
}

// ---------------- gx tile body (shared by gx kernel and helpers) ---------------
#define ROWB    144
#define TILEB   (128 * ROWB)
#define STAGEB  (2 * TILEB)
#define GXS_SMEM (2 * STAGEB)

__device__ __forceinline__ void gx_tile(unsigned dynb, int n0, int m0, int tid) {
    const int wid = tid >> 5, lid = tid & 31;
    const int wm = wid & 3, wn = wid >> 2;

    float acc[2][8][4];
    #pragma unroll
    for (int mt = 0; mt < 2; mt++)
        #pragma unroll
        for (int nt = 0; nt < 8; nt++)
            #pragma unroll
            for (int c = 0; c < 4; c++) acc[mt][nt][c] = 0.0f;

    auto load_chunk = [&](int c, int s) {
        const int k0 = c * 64;
        const unsigned sb = dynb + s * STAGEB;
        #pragma unroll
        for (int it = 0; it < 8; it++) {
            int i = tid + it * 256;
            int t = i >> 10;
            int r = (i >> 3) & 127;
            int q = i & 7;
            const __half* src = (t == 0)
                ? g_xh  + (size_t)(m0 + r) * KSEQ + k0 + q * 8
                : g_wih + (size_t)(n0 + r) * KSEQ + k0 + q * 8;
            cp16(sb + t * TILEB + r * ROWB + q * 16, src);
        }
        CP_COMMIT();
    };

    const int lrow = lid & 15;
    const int lcol = (lid >> 4) * 16;

    load_chunk(0, 0);

    for (int c = 0; c < 12; c++) {
        if (c < 11) { load_chunk(c + 1, (c + 1) & 1); CP_WAIT(1); }
        else        { CP_WAIT(0); }
        __syncthreads();

        const unsigned sb = dynb + (c & 1) * STAGEB;
        const unsigned aX = sb;
        const unsigned bW = sb + TILEB;

        #pragma unroll
        for (int k16 = 0; k16 < 4; k16++) {
            const unsigned kb = k16 * 32 + lcol;
            unsigned a[2][4], b[4][4];
            #pragma unroll
            for (int mt = 0; mt < 2; mt++)
                ldm4(a[mt], aX + (wm * 32 + mt * 16 + lrow) * ROWB + kb);
            #pragma unroll
            for (int j = 0; j < 4; j++)
                ldm4(b[j], bW + (wn * 64 + j * 16 + lrow) * ROWB + kb);
            #pragma unroll
            for (int mt = 0; mt < 2; mt++)
                #pragma unroll
                for (int j = 0; j < 4; j++) {
                    mmaf16(acc[mt][2*j],   a[mt][0], a[mt][1], a[mt][2], a[mt][3], b[j][0], b[j][2]);
                    mmaf16(acc[mt][2*j+1], a[mt][0], a[mt][1], a[mt][2], a[mt][3], b[j][1], b[j][3]);
                }
        }
        __syncthreads();
    }

    #pragma unroll
    for (int mt = 0; mt < 2; mt++) {
        int row = m0 + wm * 32 + mt * 16 + (lid >> 2);
        #pragma unroll
        for (int nt = 0; nt < 8; nt++) {
            int col = n0 + wn * 64 + nt * 8 + 2 * (lid & 3);
            float2 v0 = {acc[mt][nt][0], acc[mt][nt][1]};
            float2 v1 = {acc[mt][nt][2], acc[mt][nt][3]};
            *(float2*)&g_gx[(size_t)row * G3 + col]       = v0;
            *(float2*)&g_gx[(size_t)(row + 8) * G3 + col] = v1;
        }
    }
}

// gx kernel: only timesteps [0, TSPLIT)
__global__ __launch_bounds__(256, 2) void k_gx_mma() {
    extern __shared__ __align__(16) char dyn[];
    gx_tile(smem_u32(dyn), blockIdx.x * 128, blockIdx.y * 128, threadIdx.x);
}

// ---------------- persistent GRU recurrence + gx helpers -----------------------
#define WS_LDW 516
#define HB_ROWB 144
#define HB_BUF  (128 * HB_ROWB)
#define PERS_SMEM (24 * WS_LDW * 4 + 4 * HB_BUF)   // 123264 B (>= GXS_SMEM)

__device__ __forceinline__ void bar_arrive() {
    __syncthreads();
    if (threadIdx.x == 0)
        asm volatile("red.release.gpu.global.add.u32 [%0], 1;"
                     :: "l"(&g_count) : "memory");
}
// wait for barrier target AND (if X>0) helper gx frontier >= X
__device__ __forceinline__ void bar_wait(unsigned target, int X) {
    if (threadIdx.x == 0) {
        unsigned v;
        do {
            asm volatile("ld.acquire.gpu.global.u32 %0, [%1];"
                         : "=r"(v) : "l"(&g_count) : "memory");
        } while (v < target);
        if (X > 0) {
            int frontier;
            do {
                frontier = 0x7fffffff;
                #pragma unroll
                for (int h = 0; h < NHELP; h++) {
                    unsigned p;
                    asm volatile("ld.acquire.gpu.global.u32 %0, [%1];"
                                 : "=r"(p) : "l"(&g_hprog[h]) : "memory");
                    int f = h + NHELP * (int)p;     // smallest not-done tile of helper h
                    frontier = f < frontier ? f : frontier;
                }
            } while (frontier < X);
        }
    }
    __syncthreads();
}

__device__ __forceinline__ float sig(float x) { return 1.0f / (1.0f + __expf(-x)); }

__global__ __launch_bounds__(256) void k_gru_persist(
        const float* __restrict__ h0, const float* __restrict__ bih,
        const float* __restrict__ bhh, float* __restrict__ out, int wh)
{
    extern __shared__ __align__(16) unsigned wsm[];
    unsigned* ws = wsm;
    const unsigned wsb = smem_u32(ws);

    // ---------- helper blocks: produce gx tiles for t in [TSPLIT, 512) ----------
    if (blockIdx.x >= NBLK) {
        const int h = blockIdx.x - NBLK;
        for (int x = h; x < NTILES; x += NHELP) {
            int t  = TSPLIT + x / 24;
            int n0 = (x % 24) * 128;
            gx_tile(wsb, n0, t * 128, threadIdx.x);
            __syncthreads();
            if (threadIdx.x == 0)
                asm volatile("red.release.gpu.global.add.u32 [%0], 1;"
                             :: "l"(&g_hprog[h]) : "memory");
        }
        return;
    }

    // ---------- recurrence blocks (R10 structure, f32-acc) ----------
    const unsigned hbb = wsb + 24 * WS_LDW * 4;

    const int tid = threadIdx.x, w = tid >> 5, l = tid & 31;
    const int l4 = l & 3, n = l >> 2;
    const int j0 = blockIdx.x * 8;

    const unsigned* whh32 = (const unsigned*)g_whh;
    for (int i = tid; i < 24 * 512; i += 256) {
        int rr = i >> 9, kk = i & 511;
        int g = rr >> 3, jr = rr & 7;
        ws[rr * WS_LDW + kk] = whh32[(size_t)(g * 1024 + j0 + jr) * 512 + kk];
    }

    const int rA = w * 16 + n, rB = rA + 8;
    const int jc = j0 + l4 * 2;

    const unsigned aAddr = hbb + (unsigned)(w * 16 + (l & 15)) * HB_ROWB + (unsigned)(l >> 4) * 16;
    unsigned bAddr[3];
    #pragma unroll
    for (int g = 0; g < 3; g++)
        bAddr[g] = wsb + (unsigned)((g * 8 + (l & 7)) * WS_LDW * 4) + (unsigned)(l >> 3) * 16;

    const int srow0 = w * 16 + (l >> 3);
    const int sq16  = (l & 7) * 16;

    float biA[3][2], biB[3][2], bh[3][2];
    #pragma unroll
    for (int g = 0; g < 3; g++) {
        float b0 = bih[g * 1024 + jc], b1 = bih[g * 1024 + jc + 1];
        biA[g][0] = b0 + g_gw[(size_t)rA * G3 + g * 1024 + jc];
        biA[g][1] = b1 + g_gw[(size_t)rA * G3 + g * 1024 + jc + 1];
        biB[g][0] = b0 + g_gw[(size_t)rB * G3 + g * 1024 + jc];
        biB[g][1] = b1 + g_gw[(size_t)rB * G3 + g * 1024 + jc + 1];
        bh[g][0] = bhh[g * 1024 + jc]; bh[g][1] = bhh[g * 1024 + jc + 1];
    }

    float hA0 = h0[rA * H_DIM + jc], hA1 = h0[rA * H_DIM + jc + 1];
    float hB0 = h0[rB * H_DIM + jc], hB1 = h0[rB * H_DIM + jc + 1];

    auto wr_h = [&](unsigned* dst, int r, float v0, float v1) {
        __half2 p = {__float2half(v0), __float2half(v1)};
        __stcg(&dst[r * 512 + (jc >> 1)], *(unsigned*)&p);
    };

    float2 xA[3], xB[3];
    #pragma unroll
    for (int g = 0; g < 3; g++) {
        xA[g] = *(const float2*)&g_gx[(size_t)rA * G3 + g * 1024 + jc];
        xB[g] = *(const float2*)&g_gx[(size_t)rB * G3 + g * 1024 + jc];
    }

    wr_h((unsigned*)g_hf[0], rA, hA0, hA1);
    wr_h((unsigned*)g_hf[0], rB, hB0, hB1);
    bar_arrive();
    bar_wait(NBLK, 0);

    unsigned tgt = 2 * NBLK;
    for (int t = 0; t < T_STEPS; t++) {
        const char* hsrc = (const char*)g_hf[t & 1];
        unsigned* hnxt   = (unsigned*)g_hf[(t + 1) & 1];

        auto stage = [&](int gi) {
            if (gi < 16) {
                const unsigned db = hbb + (unsigned)(gi & 3) * HB_BUF;
                #pragma unroll
                for (int it = 0; it < 4; it++) {
                    int r = srow0 + it * 4;
                    cp16(db + (unsigned)r * HB_ROWB + sq16,
                         hsrc + (size_t)r * 2048 + gi * 128 + sq16);
                }
            }
            CP_COMMIT();
        };

        float acc[3][4];
        #pragma unroll
        for (int g = 0; g < 3; g++)
            #pragma unroll
            for (int c = 0; c < 4; c++) acc[g][c] = 0.0f;

        stage(0); stage(1); stage(2);
        #pragma unroll 1
        for (int gi = 0; gi < 16; gi++) {
            CP_WAIT(2);
            __syncwarp();
            const unsigned ab = aAddr + (unsigned)(gi & 3) * HB_BUF;
            unsigned A0[4], A1[4], A2[4], A3[4];
            ldm4(A0, ab);       ldm4(A1, ab + 32);
            ldm4(A2, ab + 64);  ldm4(A3, ab + 96);
            stage(gi + 3);
            #pragma unroll
            for (int g = 0; g < 3; g++) {
                unsigned bb[4], bb2[4];
                ldm4(bb,  bAddr[g] + gi * 128);
                ldm4(bb2, bAddr[g] + gi * 128 + 64);
                mmaf16(acc[g], A0[0], A0[1], A0[2], A0[3], bb[0],  bb[1]);
                mmaf16(acc[g], A1[0], A1[1], A1[2], A1[3], bb[2],  bb[3]);
                mmaf16(acc[g], A2[0], A2[1], A2[2], A2[3], bb2[0], bb2[1]);
                mmaf16(acc[g], A3[0], A3[1], A3[2], A3[3], bb2[2], bb2[3]);
            }
        }

        {
            float r0 = sig(xA[0].x + biA[0][0] + acc[0][0] + bh[0][0]);
            float z0 = sig(xA[1].x + biA[1][0] + acc[1][0] + bh[1][0]);
            float n0 = tanhf(xA[2].x + biA[2][0] + r0 * (acc[2][0] + bh[2][0]));
            hA0 = (1.0f - z0) * n0 + z0 * hA0;
            float r1 = sig(xA[0].y + biA[0][1] + acc[0][1] + bh[0][1]);
            float z1 = sig(xA[1].y + biA[1][1] + acc[1][1] + bh[1][1]);
            float n1 = tanhf(xA[2].y + biA[2][1] + r1 * (acc[2][1] + bh[2][1]));
            hA1 = (1.0f - z1) * n1 + z1 * hA1;
            float r2 = sig(xB[0].x + biB[0][0] + acc[0][2] + bh[0][0]);
            float z2 = sig(xB[1].x + biB[1][0] + acc[1][2] + bh[1][0]);
            float n2 = tanhf(xB[2].x + biB[2][0] + r2 * (acc[2][2] + bh[2][0]));
            hB0 = (1.0f - z2) * n2 + z2 * hB0;
            float r3 = sig(xB[0].y + biB[0][1] + acc[0][3] + bh[0][1]);
            float z3 = sig(xB[1].y + biB[1][1] + acc[1][3] + bh[1][1]);
            float n3 = tanhf(xB[2].y + biB[2][1] + r3 * (acc[2][3] + bh[2][1]));
            hB1 = (1.0f - z3) * n3 + z3 * hB1;
        }

        float2 oA = {hA0, hA1}, oB = {hB0, hB1};
        wr_h(hnxt, rA, hA0, hA1);
        wr_h(hnxt, rB, hB0, hB1);

        if (t == T_STEPS - 1) {
            *(float2*)&out[((size_t)t * B_SZ + rA) * H_DIM + jc] = oA;
            *(float2*)&out[((size_t)t * B_SZ + rB) * H_DIM + jc] = oB;
            if (wh) {
                *(float2*)&out[(size_t)M_TOT * H_DIM + (size_t)rA * H_DIM + jc] = oA;
                *(float2*)&out[(size_t)M_TOT * H_DIM + (size_t)rB * H_DIM + jc] = oB;
            }
        } else {
            bar_arrive();
            *(float2*)&out[((size_t)t * B_SZ + rA) * H_DIM + jc] = oA;
            *(float2*)&out[((size_t)t * B_SZ + rB) * H_DIM + jc] = oB;
            const float* gxn = g_gx + (size_t)(t + 1) * B_SZ * G3;
            if (t + 1 < TSPLIT) {
                // gx[t+1] precomputed: prefetch inside barrier slack
                #pragma unroll
                for (int g = 0; g < 3; g++) {
                    xA[g] = *(const float2*)&gxn[(size_t)rA * G3 + g * 1024 + jc];
                    xB[g] = *(const float2*)&gxn[(size_t)rB * G3 + g * 1024 + jc];
                }
                bar_wait(tgt, 0);
            } else {
                // helper-produced: wait for tiles of step t+1 before loading
                bar_wait(tgt, (t + 2 - TSPLIT) * 24);
                #pragma unroll
                for (int g = 0; g < 3; g++) {
                    xA[g] = *(const float2*)&gxn[(size_t)rA * G3 + g * 1024 + jc];
                    xB[g] = *(const float2*)&gxn[(size_t)rB * G3 + g * 1024 + jc];
                }
            }
            tgt += NBLK;
        }
    }
}

// ---------------- launch ------------------------------------------------------
extern "C" void kernel_launch(void* const* d_in, const int* in_sizes, int n_in,
                              void* d_out, int out_size) {
    const float* seq  = (const float*)d_in[0];
    const float* word = (const float*)d_in[1];
    const float* h0   = (const float*)d_in[2];
    const float* wih  = (const float*)d_in[3];
    const float* whh  = (const float*)d_in[4];
    const float* bih  = (const float*)d_in[5];
    const float* bhh  = (const float*)d_in[6];
    float* out = (float*)d_out;
    (void)in_sizes; (void)n_in;

    cudaFuncSetAttribute(k_gx_mma, cudaFuncAttributeMaxDynamicSharedMemorySize, GXS_SMEM);
    cudaFuncSetAttribute(k_gru_persist, cudaFuncAttributeMaxDynamicSharedMemorySize, PERS_SMEM);

    const int hidden_ok = (out_size >= T_STEPS * B_SZ * H_DIM + B_SZ * H_DIM) ? 1 : 0;

    k_prep1<<<12288 + 128, 256>>>(whh, word, wih);
    k_prep2<<<9216 + 49152, 256>>>(wih, seq);
    k_gx_mma<<<dim3(G3 / 128, TSPLIT), 256, GXS_SMEM>>>();
    k_gru_persist<<<NBLK + NHELP, 256, PERS_SMEM>>>(h0, bih, bhh, out, hidden_ok);
}

// round 15
// speedup vs baseline: 1.1553x; 1.0802x over previous
#include <cuda_runtime.h>
#include <cuda_fp16.h>
#include <cstdint>
#include <cstddef>

#define T_STEPS 512
#define B_SZ    128
#define E_SEQ   768
#define COND    256
#define H_DIM   1024
#define KSEQ    768
#define G3      3072
#define M_TOT   (T_STEPS * B_SZ)
#define NBLK    128

// ---------------- static device scratch --------------------------------------
__device__ float   g_gx[(size_t)M_TOT * G3];
__device__ float   g_gw[(size_t)B_SZ * G3];
__device__ __half  g_whh[(size_t)G3 * H_DIM];
__device__ __half  g_wih[(size_t)G3 * KSEQ];
__device__ __half  g_xh[(size_t)M_TOT * KSEQ];
__device__ __half  g_hf[2][B_SZ * H_DIM];
__device__ unsigned g_count;

// ---------------- fused prep (1 kernel; persist stays launch #3... #4 w/ gx) --
// blocks [0,12288): whh->fp16 ; [12288,21504): wih seq-cols ; [21504,70656): xh ;
// [70656,70784): word GEMV + init
__global__ __launch_bounds__(256) void k_prep(const float* __restrict__ whh,
                                              const float* __restrict__ wih,
                                              const float* __restrict__ seq,
                                              const float* __restrict__ word) {
    const int tid = threadIdx.x;
    if (blockIdx.x < 12288) {
        int i = blockIdx.x * 256 + tid;
        g_whh[i] = __float2half(whh[i]);
        return;
    }
    if (blockIdx.x < 21504) {
        int i = (blockIdx.x - 12288) * 256 + tid;
        int j = i / KSEQ, k = i - j * KSEQ;
        g_wih[i] = __float2half(wih[(size_t)j * (COND + KSEQ) + COND + k]);
        return;
    }
    if (blockIdx.x < 70656) {
        size_t i = (size_t)(blockIdx.x - 21504) * 256 + tid;
        if (i >= (size_t)M_TOT * KSEQ / 4) return;
        float4 v = ((const float4*)seq)[i];
        __half2 p0 = {__float2half(v.x), __float2half(v.y)};
        __half2 p1 = {__float2half(v.z), __float2half(v.w)};
        ((__half2*)g_xh)[2 * i]     = p0;
        ((__half2*)g_xh)[2 * i + 1] = p1;
        return;
    }
    __shared__ float wrow[COND];
    const int b = blockIdx.x - 70656;
    if (b == 0 && tid == 0) g_count = 0u;
    if (tid < COND) wrow[tid] = word[b * COND + tid];
    __syncthreads();
    for (int j = tid; j < G3; j += 256) {
        const float4* wr = (const float4*)&wih[(size_t)j * (COND + KSEQ)];
        float s = 0.0f;
        #pragma unroll 8
        for (int k = 0; k < COND / 4; k++) {
            float4 wv = wr[k];
            s += wv.x * wrow[4*k] + wv.y * wrow[4*k+1] + wv.z * wrow[4*k+2] + wv.w * wrow[4*k+3];
        }
        g_gw[(size_t)b * G3 + j] = s;
    }
}

// ---------------- PTX helpers --------------------------------------------------
__device__ __forceinline__ unsigned smem_u32(const void* p) {
    return (unsigned)__cvta_generic_to_shared(p);
}
__device__ __forceinline__ void cp16(unsigned dst, const void* src) {
    asm volatile("cp.async.cg.shared.global [%0], [%1], 16;\n" :: "r"(dst), "l"(src));
}
#define CP_COMMIT()  asm volatile("cp.async.commit_group;\n")
#define CP_WAIT(n)   asm volatile("cp.async.wait_group %0;\n" :: "n"(n))

__device__ __forceinline__ void ldm4(unsigned r[4], unsigned addr) {
    asm volatile("ldmatrix.sync.aligned.m8n8.x4.shared.b16 {%0,%1,%2,%3}, [%4];"
        : "=r"(r[0]), "=r"(r[1]), "=r"(r[2]), "=r"(r[3]) : "r"(addr));
}
__device__ __forceinline__ void mmaf16(float c[4], unsigned a0, unsigned a1,
                                       unsigned a2, unsigned a3,
                                       unsigned b0, unsigned b1) {
    asm volatile(
        "mma.sync.aligned.m16n8k16.row.col.f32.f16.f16.f32 "
        "{%0,%1,%2,%3},{%4,%5,%6,%7},{%8,%9},{%0,%1,%2,%3};\n"
        : "+f"(c[0]), "+f"(c[1]), "+f"(c[2]), "+f"(c[3])
        : "r"(a0), "r"(a1), "r"(a2), "r"(a3), "r"(b0), "r"(b1));
}
// fast activations via MUFU.TANH
__device__ __forceinline__ float ftanh(float x) {
    float r;
    asm("tanh.approx.f32 %0, %1;" : "=f"(r) : "f"(x));
    return r;
}
__device__ __forceinline__ float fsig(float x) {
    return fmaf(ftanh(x * 0.5f), 0.5f, 0.5f);
}

// ---------------- gx GEMM (seq part): 128x128 CTA, fp16, f32-acc (proven) -----
#define ROWB    144
#define TILEB   (128 * ROWB)
#define STAGEB  (2 * TILEB)
#define GXS_SMEM (2 * STAGEB)

__global__ __launch_bounds__(256, 2) void k_gx_mma() {
    extern __shared__ __align__(16) char dyn[];
    const unsigned dynb = smem_u32(dyn);

    const int tid = threadIdx.x;
    const int wid = tid >> 5, lid = tid & 31;
    const int wm = wid & 3, wn = wid >> 2;
    const int n0 = blockIdx.x * 128;
    const int m0 = blockIdx.y * 128;

    float acc[2][8][4];
    #pragma unroll
    for (int mt = 0; mt < 2; mt++)
        #pragma unroll
        for (int nt = 0; nt < 8; nt++)
            #pragma unroll
            for (int c = 0; c < 4; c++) acc[mt][nt][c] = 0.0f;

    auto load_chunk = [&](int c, int s) {
        const int k0 = c * 64;
        const unsigned sb = dynb + s * STAGEB;
        #pragma unroll
        for (int it = 0; it < 8; it++) {
            int i = tid + it * 256;
            int t = i >> 10;
            int r = (i >> 3) & 127;
            int q = i & 7;
            const __half* src = (t == 0)
                ? g_xh  + (size_t)(m0 + r) * KSEQ + k0 + q * 8
                : g_wih + (size_t)(n0 + r) * KSEQ + k0 + q * 8;
            cp16(sb + t * TILEB + r * ROWB + q * 16, src);
        }
        CP_COMMIT();
    };

    const int lrow = lid & 15;
    const int lcol = (lid >> 4) * 16;

    load_chunk(0, 0);

    for (int c = 0; c < 12; c++) {
        if (c < 11) { load_chunk(c + 1, (c + 1) & 1); CP_WAIT(1); }
        else        { CP_WAIT(0); }
        __syncthreads();

        const unsigned sb = dynb + (c & 1) * STAGEB;
        const unsigned aX = sb;
        const unsigned bW = sb + TILEB;

        #pragma unroll
        for (int k16 = 0; k16 < 4; k16++) {
            const unsigned kb = k16 * 32 + lcol;
            unsigned a[2][4], b[4][4];
            #pragma unroll
            for (int mt = 0; mt < 2; mt++)
                ldm4(a[mt], aX + (wm * 32 + mt * 16 + lrow) * ROWB + kb);
            #pragma unroll
            for (int j = 0; j < 4; j++)
                ldm4(b[j], bW + (wn * 64 + j * 16 + lrow) * ROWB + kb);
            #pragma unroll
            for (int mt = 0; mt < 2; mt++)
                #pragma unroll
                for (int j = 0; j < 4; j++) {
                    mmaf16(acc[mt][2*j],   a[mt][0], a[mt][1], a[mt][2], a[mt][3], b[j][0], b[j][2]);
                    mmaf16(acc[mt][2*j+1], a[mt][0], a[mt][1], a[mt][2], a[mt][3], b[j][1], b[j][3]);
                }
        }
        __syncthreads();
    }

    #pragma unroll
    for (int mt = 0; mt < 2; mt++) {
        int row = m0 + wm * 32 + mt * 16 + (lid >> 2);
        #pragma unroll
        for (int nt = 0; nt < 8; nt++) {
            int col = n0 + wn * 64 + nt * 8 + 2 * (lid & 3);
            float2 v0 = {acc[mt][nt][0], acc[mt][nt][1]};
            float2 v1 = {acc[mt][nt][2], acc[mt][nt][3]};
            *(float2*)&g_gx[(size_t)row * G3 + col]       = v0;
            *(float2*)&g_gx[(size_t)(row + 8) * G3 + col] = v1;
        }
    }
}

// ---------------- persistent GRU recurrence (R10 proven, fast activations) -----
#define WS_LDW 516
#define HB_ROWB 144
#define HB_BUF  (128 * HB_ROWB)
#define PERS_SMEM (24 * WS_LDW * 4 + 4 * HB_BUF)   // 123264 B

__device__ __forceinline__ void bar_arrive() {
    __syncthreads();
    if (threadIdx.x == 0)
        asm volatile("red.release.gpu.global.add.u32 [%0], 1;"
                     :: "l"(&g_count) : "memory");
}
__device__ __forceinline__ void bar_wait(unsigned target) {
    if (threadIdx.x == 0) {
        unsigned v;
        do {
            asm volatile("ld.acquire.gpu.global.u32 %0, [%1];"
                         : "=r"(v) : "l"(&g_count) : "memory");
        } while (v < target);
    }
    __syncthreads();
}

__global__ __launch_bounds__(256) void k_gru_persist(
        const float* __restrict__ h0, const float* __restrict__ bih,
        const float* __restrict__ bhh, float* __restrict__ out, int wh)
{
    extern __shared__ __align__(16) unsigned wsm[];
    unsigned* ws = wsm;
    const unsigned wsb = smem_u32(ws);
    const unsigned hbb = wsb + 24 * WS_LDW * 4;

    const int tid = threadIdx.x, w = tid >> 5, l = tid & 31;
    const int l4 = l & 3, n = l >> 2;
    const int j0 = blockIdx.x * 8;

    const unsigned* whh32 = (const unsigned*)g_whh;
    for (int i = tid; i < 24 * 512; i += 256) {
        int rr = i >> 9, kk = i & 511;
        int g = rr >> 3, jr = rr & 7;
        ws[rr * WS_LDW + kk] = whh32[(size_t)(g * 1024 + j0 + jr) * 512 + kk];
    }

    const int rA = w * 16 + n, rB = rA + 8;
    const int jc = j0 + l4 * 2;

    const unsigned aAddr = hbb + (unsigned)(w * 16 + (l & 15)) * HB_ROWB + (unsigned)(l >> 4) * 16;
    unsigned bAddr[3];
    #pragma unroll
    for (int g = 0; g < 3; g++)
        bAddr[g] = wsb + (unsigned)((g * 8 + (l & 7)) * WS_LDW * 4) + (unsigned)(l >> 3) * 16;

    const int srow0 = w * 16 + (l >> 3);
    const int sq16  = (l & 7) * 16;

    float biA[3][2], biB[3][2], bh[3][2];
    #pragma unroll
    for (int g = 0; g < 3; g++) {
        float b0 = bih[g * 1024 + jc], b1 = bih[g * 1024 + jc + 1];
        biA[g][0] = b0 + g_gw[(size_t)rA * G3 + g * 1024 + jc];
        biA[g][1] = b1 + g_gw[(size_t)rA * G3 + g * 1024 + jc + 1];
        biB[g][0] = b0 + g_gw[(size_t)rB * G3 + g * 1024 + jc];
        biB[g][1] = b1 + g_gw[(size_t)rB * G3 + g * 1024 + jc + 1];
        bh[g][0] = bhh[g * 1024 + jc]; bh[g][1] = bhh[g * 1024 + jc + 1];
    }

    float hA0 = h0[rA * H_DIM + jc], hA1 = h0[rA * H_DIM + jc + 1];
    float hB0 = h0[rB * H_DIM + jc], hB1 = h0[rB * H_DIM + jc + 1];

    auto wr_h = [&](unsigned* dst, int r, float v0, float v1) {
        __half2 p = {__float2half(v0), __float2half(v1)};
        __stcg(&dst[r * 512 + (jc >> 1)], *(unsigned*)&p);
    };

    float2 xA[3], xB[3];
    #pragma unroll
    for (int g = 0; g < 3; g++) {
        xA[g] = *(const float2*)&g_gx[(size_t)rA * G3 + g * 1024 + jc];
        xB[g] = *(const float2*)&g_gx[(size_t)rB * G3 + g * 1024 + jc];
    }

    wr_h((unsigned*)g_hf[0], rA, hA0, hA1);
    wr_h((unsigned*)g_hf[0], rB, hB0, hB1);
    bar_arrive();
    bar_wait(NBLK);

    unsigned tgt = 2 * NBLK;
    for (int t = 0; t < T_STEPS; t++) {
        const char* hsrc = (const char*)g_hf[t & 1];
        unsigned* hnxt   = (unsigned*)g_hf[(t + 1) & 1];

        auto stage = [&](int gi) {
            if (gi < 16) {
                const unsigned db = hbb + (unsigned)(gi & 3) * HB_BUF;
                #pragma unroll
                for (int it = 0; it < 4; it++) {
                    int r = srow0 + it * 4;
                    cp16(db + (unsigned)r * HB_ROWB + sq16,
                         hsrc + (size_t)r * 2048 + gi * 128 + sq16);
                }
            }
            CP_COMMIT();
        };

        float acc[3][4];
        #pragma unroll
        for (int g = 0; g < 3; g++)
            #pragma unroll
            for (int c = 0; c < 4; c++) acc[g][c] = 0.0f;

        stage(0); stage(1); stage(2);
        #pragma unroll 1
        for (int gi = 0; gi < 16; gi++) {
            CP_WAIT(2);
            __syncwarp();
            const unsigned ab = aAddr + (unsigned)(gi & 3) * HB_BUF;
            unsigned A0[4], A1[4], A2[4], A3[4];
            ldm4(A0, ab);       ldm4(A1, ab + 32);
            ldm4(A2, ab + 64);  ldm4(A3, ab + 96);
            stage(gi + 3);
            #pragma unroll
            for (int g = 0; g < 3; g++) {
                unsigned bb[4], bb2[4];
                ldm4(bb,  bAddr[g] + gi * 128);
                ldm4(bb2, bAddr[g] + gi * 128 + 64);
                mmaf16(acc[g], A0[0], A0[1], A0[2], A0[3], bb[0],  bb[1]);
                mmaf16(acc[g], A1[0], A1[1], A1[2], A1[3], bb[2],  bb[3]);
                mmaf16(acc[g], A2[0], A2[1], A2[2], A2[3], bb2[0], bb2[1]);
                mmaf16(acc[g], A3[0], A3[1], A3[2], A3[3], bb2[2], bb2[3]);
            }
        }

        {
            float r0 = fsig(xA[0].x + biA[0][0] + acc[0][0] + bh[0][0]);
            float z0 = fsig(xA[1].x + biA[1][0] + acc[1][0] + bh[1][0]);
            float n0 = ftanh(xA[2].x + biA[2][0] + r0 * (acc[2][0] + bh[2][0]));
            hA0 = (1.0f - z0) * n0 + z0 * hA0;
            float r1 = fsig(xA[0].y + biA[0][1] + acc[0][1] + bh[0][1]);
            float z1 = fsig(xA[1].y + biA[1][1] + acc[1][1] + bh[1][1]);
            float n1 = ftanh(xA[2].y + biA[2][1] + r1 * (acc[2][1] + bh[2][1]));
            hA1 = (1.0f - z1) * n1 + z1 * hA1;
            float r2 = fsig(xB[0].x + biB[0][0] + acc[0][2] + bh[0][0]);
            float z2 = fsig(xB[1].x + biB[1][0] + acc[1][2] + bh[1][0]);
            float n2 = ftanh(xB[2].x + biB[2][0] + r2 * (acc[2][2] + bh[2][0]));
            hB0 = (1.0f - z2) * n2 + z2 * hB0;
            float r3 = fsig(xB[0].y + biB[0][1] + acc[0][3] + bh[0][1]);
            float z3 = fsig(xB[1].y + biB[1][1] + acc[1][3] + bh[1][1]);
            float n3 = ftanh(xB[2].y + biB[2][1] + r3 * (acc[2][3] + bh[2][1]));
            hB1 = (1.0f - z3) * n3 + z3 * hB1;
        }

        float2 oA = {hA0, hA1}, oB = {hB0, hB1};
        wr_h(hnxt, rA, hA0, hA1);
        wr_h(hnxt, rB, hB0, hB1);

        if (t == T_STEPS - 1) {
            *(float2*)&out[((size_t)t * B_SZ + rA) * H_DIM + jc] = oA;
            *(float2*)&out[((size_t)t * B_SZ + rB) * H_DIM + jc] = oB;
            if (wh) {
                *(float2*)&out[(size_t)M_TOT * H_DIM + (size_t)rA * H_DIM + jc] = oA;
                *(float2*)&out[(size_t)M_TOT * H_DIM + (size_t)rB * H_DIM + jc] = oB;
            }
        } else {
            bar_arrive();
            *(float2*)&out[((size_t)t * B_SZ + rA) * H_DIM + jc] = oA;
            *(float2*)&out[((size_t)t * B_SZ + rB) * H_DIM + jc] = oB;
            const float* gxn = g_gx + (size_t)(t + 1) * B_SZ * G3;
            #pragma unroll
            for (int g = 0; g < 3; g++) {
                xA[g] = *(const float2*)&gxn[(size_t)rA * G3 + g * 1024 + jc];
                xB[g] = *(const float2*)&gxn[(size_t)rB * G3 + g * 1024 + jc];
            }
            bar_wait(tgt);
            tgt += NBLK;
        }
    }
}

// ---------------- launch ------------------------------------------------------
extern "C" void kernel_launch(void* const* d_in, const int* in_sizes, int n_in,
                              void* d_out, int out_size) {
    const float* seq  = (const float*)d_in[0];
    const float* word = (const float*)d_in[1];
    const float* h0   = (const float*)d_in[2];
    const float* wih  = (const float*)d_in[3];
    const float* whh  = (const float*)d_in[4];
    const float* bih  = (const float*)d_in[5];
    const float* bhh  = (const float*)d_in[6];
    float* out = (float*)d_out;
    (void)in_sizes; (void)n_in;

    cudaFuncSetAttribute(k_gx_mma, cudaFuncAttributeMaxDynamicSharedMemorySize, GXS_SMEM);
    cudaFuncSetAttribute(k_gru_persist, cudaFuncAttributeMaxDynamicSharedMemorySize, PERS_SMEM);

    const int hidden_ok = (out_size >= T_STEPS * B_SZ * H_DIM + B_SZ * H_DIM) ? 1 : 0;

    k_prep<<<70656 + 128, 256>>>(whh, wih, seq, word);
    k_gx_mma<<<dim3(G3 / 128, M_TOT / 128), 256, GXS_SMEM>>>();
    k_gru_persist<<<NBLK, 256, PERS_SMEM>>>(h0, bih, bhh, out, hidden_ok);
}

// round 16
// speedup vs baseline: 1.2025x; 1.0408x over previous
#include <cuda_runtime.h>
#include <cuda_fp16.h>
#include <cstdint>
#include <cstddef>

#define T_STEPS 512
#define B_SZ    128
#define E_SEQ   768
#define COND    256
#define H_DIM   1024
#define KSEQ    768
#define G3      3072
#define M_TOT   (T_STEPS * B_SZ)
#define NBLK    128

// ---------------- static device scratch --------------------------------------
__device__ float   g_gx[(size_t)M_TOT * G3];
__device__ float   g_gw[(size_t)B_SZ * G3];
__device__ __half  g_whh[(size_t)G3 * H_DIM];
__device__ __half  g_wih[(size_t)G3 * KSEQ];
__device__ __half  g_xh[(size_t)M_TOT * KSEQ];
__device__ __half  g_hf[2][B_SZ * H_DIM];
__device__ unsigned g_count;

// ---------------- prep kernels (split: low-reg, memory-bound) -----------------
__global__ void k_cvt_whh(const float* __restrict__ w) {
    int i = blockIdx.x * blockDim.x + threadIdx.x;
    if (i == 0) g_count = 0u;
    if (i < G3 * H_DIM) g_whh[i] = __float2half(w[i]);
}
__global__ void k_cvt_wih(const float* __restrict__ w) {
    int i = blockIdx.x * blockDim.x + threadIdx.x;
    if (i < G3 * KSEQ) {
        int j = i / KSEQ, k = i - j * KSEQ;
        g_wih[i] = __float2half(w[(size_t)j * (COND + KSEQ) + COND + k]);
    }
}
__global__ void k_xh(const float* __restrict__ seq) {
    size_t i = (size_t)blockIdx.x * blockDim.x + threadIdx.x;
    if (i >= (size_t)M_TOT * KSEQ / 4) return;
    float4 v = ((const float4*)seq)[i];
    __half2 p0 = {__float2half(v.x), __float2half(v.y)};
    __half2 p1 = {__float2half(v.z), __float2half(v.w)};
    ((__half2*)g_xh)[2 * i]     = p0;
    ((__half2*)g_xh)[2 * i + 1] = p1;
}
__global__ __launch_bounds__(256) void k_word(const float* __restrict__ word,
                                              const float* __restrict__ wih) {
    __shared__ float wrow[COND];
    const int b = blockIdx.x, tid = threadIdx.x;
    if (tid < COND) wrow[tid] = word[b * COND + tid];
    __syncthreads();
    for (int j = tid; j < G3; j += 256) {
        const float4* wr = (const float4*)&wih[(size_t)j * (COND + KSEQ)];
        float s = 0.0f;
        #pragma unroll 8
        for (int k = 0; k < COND / 4; k++) {
            float4 wv = wr[k];
            s += wv.x * wrow[4*k] + wv.y * wrow[4*k+1] + wv.z * wrow[4*k+2] + wv.w * wrow[4*k+3];
        }
        g_gw[(size_t)b * G3 + j] = s;
    }
}

// ---------------- PTX helpers --------------------------------------------------
__device__ __forceinline__ unsigned smem_u32(const void* p) {
    return (unsigned)__cvta_generic_to_shared(p);
}
__device__ __forceinline__ void cp16(unsigned dst, const void* src) {
    asm volatile("cp.async.cg.shared.global [%0], [%1], 16;\n" :: "r"(dst), "l"(src));
}
#define CP_COMMIT()  asm volatile("cp.async.commit_group;\n")
#define CP_WAIT(n)   asm volatile("cp.async.wait_group %0;\n" :: "n"(n))

__device__ __forceinline__ void ldm4(unsigned r[4], unsigned addr) {
    asm volatile("ldmatrix.sync.aligned.m8n8.x4.shared.b16 {%0,%1,%2,%3}, [%4];"
        : "=r"(r[0]), "=r"(r[1]), "=r"(r[2]), "=r"(r[3]) : "r"(addr));
}
__device__ __forceinline__ void mmaf16(float c[4], unsigned a0, unsigned a1,
                                       unsigned a2, unsigned a3,
                                       unsigned b0, unsigned b1) {
    asm volatile(
        "mma.sync.aligned.m16n8k16.row.col.f32.f16.f16.f32 "
        "{%0,%1,%2,%3},{%4,%5,%6,%7},{%8,%9},{%0,%1,%2,%3};\n"
        : "+f"(c[0]), "+f"(c[1]), "+f"(c[2]), "+f"(c[3])
        : "r"(a0), "r"(a1), "r"(a2), "r"(a3), "r"(b0), "r"(b1));
}
// fast activations via MUFU.TANH
__device__ __forceinline__ float ftanh(float x) {
    float r;
    asm("tanh.approx.f32 %0, %1;" : "=f"(r) : "f"(x));
    return r;
}
__device__ __forceinline__ float fsig(float x) {
    return fmaf(ftanh(x * 0.5f), 0.5f, 0.5f);
}

// ---------------- gx GEMM (seq part): 128x128 CTA, fp16, f32-acc (proven) -----
#define ROWB    144
#define TILEB   (128 * ROWB)
#define STAGEB  (2 * TILEB)
#define GXS_SMEM (2 * STAGEB)

__global__ __launch_bounds__(256, 2) void k_gx_mma() {
    extern __shared__ __align__(16) char dyn[];
    const unsigned dynb = smem_u32(dyn);

    const int tid = threadIdx.x;
    const int wid = tid >> 5, lid = tid & 31;
    const int wm = wid & 3, wn = wid >> 2;
    const int n0 = blockIdx.x * 128;
    const int m0 = blockIdx.y * 128;

    float acc[2][8][4];
    #pragma unroll
    for (int mt = 0; mt < 2; mt++)
        #pragma unroll
        for (int nt = 0; nt < 8; nt++)
            #pragma unroll
            for (int c = 0; c < 4; c++) acc[mt][nt][c] = 0.0f;

    auto load_chunk = [&](int c, int s) {
        const int k0 = c * 64;
        const unsigned sb = dynb + s * STAGEB;
        #pragma unroll
        for (int it = 0; it < 8; it++) {
            int i = tid + it * 256;
            int t = i >> 10;
            int r = (i >> 3) & 127;
            int q = i & 7;
            const __half* src = (t == 0)
                ? g_xh  + (size_t)(m0 + r) * KSEQ + k0 + q * 8
                : g_wih + (size_t)(n0 + r) * KSEQ + k0 + q * 8;
            cp16(sb + t * TILEB + r * ROWB + q * 16, src);
        }
        CP_COMMIT();
    };

    const int lrow = lid & 15;
    const int lcol = (lid >> 4) * 16;

    load_chunk(0, 0);

    for (int c = 0; c < 12; c++) {
        if (c < 11) { load_chunk(c + 1, (c + 1) & 1); CP_WAIT(1); }
        else        { CP_WAIT(0); }
        __syncthreads();

        const unsigned sb = dynb + (c & 1) * STAGEB;
        const unsigned aX = sb;
        const unsigned bW = sb + TILEB;

        #pragma unroll
        for (int k16 = 0; k16 < 4; k16++) {
            const unsigned kb = k16 * 32 + lcol;
            unsigned a[2][4], b[4][4];
            #pragma unroll
            for (int mt = 0; mt < 2; mt++)
                ldm4(a[mt], aX + (wm * 32 + mt * 16 + lrow) * ROWB + kb);
            #pragma unroll
            for (int j = 0; j < 4; j++)
                ldm4(b[j], bW + (wn * 64 + j * 16 + lrow) * ROWB + kb);
            #pragma unroll
            for (int mt = 0; mt < 2; mt++)
                #pragma unroll
                for (int j = 0; j < 4; j++) {
                    mmaf16(acc[mt][2*j],   a[mt][0], a[mt][1], a[mt][2], a[mt][3], b[j][0], b[j][2]);
                    mmaf16(acc[mt][2*j+1], a[mt][0], a[mt][1], a[mt][2], a[mt][3], b[j][1], b[j][3]);
                }
        }
        __syncthreads();
    }

    #pragma unroll
    for (int mt = 0; mt < 2; mt++) {
        int row = m0 + wm * 32 + mt * 16 + (lid >> 2);
        #pragma unroll
        for (int nt = 0; nt < 8; nt++) {
            int col = n0 + wn * 64 + nt * 8 + 2 * (lid & 3);
            float2 v0 = {acc[mt][nt][0], acc[mt][nt][1]};
            float2 v1 = {acc[mt][nt][2], acc[mt][nt][3]};
            *(float2*)&g_gx[(size_t)row * G3 + col]       = v0;
            *(float2*)&g_gx[(size_t)(row + 8) * G3 + col] = v1;
        }
    }
}

// ---------------- persistent GRU recurrence (R15 proven) -----------------------
#define WS_LDW 516
#define HB_ROWB 144
#define HB_BUF  (128 * HB_ROWB)
#define PERS_SMEM (24 * WS_LDW * 4 + 4 * HB_BUF)   // 123264 B

__device__ __forceinline__ void bar_arrive() {
    __syncthreads();
    if (threadIdx.x == 0)
        asm volatile("red.release.gpu.global.add.u32 [%0], 1;"
                     :: "l"(&g_count) : "memory");
}
__device__ __forceinline__ void bar_wait(unsigned target) {
    if (threadIdx.x == 0) {
        unsigned v;
        do {
            asm volatile("ld.acquire.gpu.global.u32 %0, [%1];"
                         : "=r"(v) : "l"(&g_count) : "memory");
        } while (v < target);
    }
    __syncthreads();
}

__global__ __launch_bounds__(256) void k_gru_persist(
        const float* __restrict__ h0, const float* __restrict__ bih,
        const float* __restrict__ bhh, float* __restrict__ out, int wh)
{
    extern __shared__ __align__(16) unsigned wsm[];
    unsigned* ws = wsm;
    const unsigned wsb = smem_u32(ws);
    const unsigned hbb = wsb + 24 * WS_LDW * 4;

    const int tid = threadIdx.x, w = tid >> 5, l = tid & 31;
    const int l4 = l & 3, n = l >> 2;
    const int j0 = blockIdx.x * 8;

    const unsigned* whh32 = (const unsigned*)g_whh;
    for (int i = tid; i < 24 * 512; i += 256) {
        int rr = i >> 9, kk = i & 511;
        int g = rr >> 3, jr = rr & 7;
        ws[rr * WS_LDW + kk] = whh32[(size_t)(g * 1024 + j0 + jr) * 512 + kk];
    }

    const int rA = w * 16 + n, rB = rA + 8;
    const int jc = j0 + l4 * 2;

    const unsigned aAddr = hbb + (unsigned)(w * 16 + (l & 15)) * HB_ROWB + (unsigned)(l >> 4) * 16;
    unsigned bAddr[3];
    #pragma unroll
    for (int g = 0; g < 3; g++)
        bAddr[g] = wsb + (unsigned)((g * 8 + (l & 7)) * WS_LDW * 4) + (unsigned)(l >> 3) * 16;

    const int srow0 = w * 16 + (l >> 3);
    const int sq16  = (l & 7) * 16;

    float biA[3][2], biB[3][2], bh[3][2];
    #pragma unroll
    for (int g = 0; g < 3; g++) {
        float b0 = bih[g * 1024 + jc], b1 = bih[g * 1024 + jc + 1];
        biA[g][0] = b0 + g_gw[(size_t)rA * G3 + g * 1024 + jc];
        biA[g][1] = b1 + g_gw[(size_t)rA * G3 + g * 1024 + jc + 1];
        biB[g][0] = b0 + g_gw[(size_t)rB * G3 + g * 1024 + jc];
        biB[g][1] = b1 + g_gw[(size_t)rB * G3 + g * 1024 + jc + 1];
        bh[g][0] = bhh[g * 1024 + jc]; bh[g][1] = bhh[g * 1024 + jc + 1];
    }

    float hA0 = h0[rA * H_DIM + jc], hA1 = h0[rA * H_DIM + jc + 1];
    float hB0 = h0[rB * H_DIM + jc], hB1 = h0[rB * H_DIM + jc + 1];

    auto wr_h = [&](unsigned* dst, int r, float v0, float v1) {
        __half2 p = {__float2half(v0), __float2half(v1)};
        __stcg(&dst[r * 512 + (jc >> 1)], *(unsigned*)&p);
    };

    float2 xA[3], xB[3];
    #pragma unroll
    for (int g = 0; g < 3; g++) {
        xA[g] = *(const float2*)&g_gx[(size_t)rA * G3 + g * 1024 + jc];
        xB[g] = *(const float2*)&g_gx[(size_t)rB * G3 + g * 1024 + jc];
    }

    wr_h((unsigned*)g_hf[0], rA, hA0, hA1);
    wr_h((unsigned*)g_hf[0], rB, hB0, hB1);
    bar_arrive();
    bar_wait(NBLK);

    unsigned tgt = 2 * NBLK;
    for (int t = 0; t < T_STEPS; t++) {
        const char* hsrc = (const char*)g_hf[t & 1];
        unsigned* hnxt   = (unsigned*)g_hf[(t + 1) & 1];

        auto stage = [&](int gi) {
            if (gi < 16) {
                const unsigned db = hbb + (unsigned)(gi & 3) * HB_BUF;
                #pragma unroll
                for (int it = 0; it < 4; it++) {
                    int r = srow0 + it * 4;
                    cp16(db + (unsigned)r * HB_ROWB + sq16,
                         hsrc + (size_t)r * 2048 + gi * 128 + sq16);
                }
            }
            CP_COMMIT();
        };

        float acc[3][4];
        #pragma unroll
        for (int g = 0; g < 3; g++)
            #pragma unroll
            for (int c = 0; c < 4; c++) acc[g][c] = 0.0f;

        stage(0); stage(1); stage(2);
        #pragma unroll 1
        for (int gi = 0; gi < 16; gi++) {
            CP_WAIT(2);
            __syncwarp();
            const unsigned ab = aAddr + (unsigned)(gi & 3) * HB_BUF;
            unsigned A0[4], A1[4], A2[4], A3[4];
            ldm4(A0, ab);       ldm4(A1, ab + 32);
            ldm4(A2, ab + 64);  ldm4(A3, ab + 96);
            stage(gi + 3);
            #pragma unroll
            for (int g = 0; g < 3; g++) {
                unsigned bb[4], bb2[4];
                ldm4(bb,  bAddr[g] + gi * 128);
                ldm4(bb2, bAddr[g] + gi * 128 + 64);
                mmaf16(acc[g], A0[0], A0[1], A0[2], A0[3], bb[0],  bb[1]);
                mmaf16(acc[g], A1[0], A1[1], A1[2], A1[3], bb[2],  bb[3]);
                mmaf16(acc[g], A2[0], A2[1], A2[2], A2[3], bb2[0], bb2[1]);
                mmaf16(acc[g], A3[0], A3[1], A3[2], A3[3], bb2[2], bb2[3]);
            }
        }

        {
            float r0 = fsig(xA[0].x + biA[0][0] + acc[0][0] + bh[0][0]);
            float z0 = fsig(xA[1].x + biA[1][0] + acc[1][0] + bh[1][0]);
            float n0 = ftanh(xA[2].x + biA[2][0] + r0 * (acc[2][0] + bh[2][0]));
            hA0 = (1.0f - z0) * n0 + z0 * hA0;
            float r1 = fsig(xA[0].y + biA[0][1] + acc[0][1] + bh[0][1]);
            float z1 = fsig(xA[1].y + biA[1][1] + acc[1][1] + bh[1][1]);
            float n1 = ftanh(xA[2].y + biA[2][1] + r1 * (acc[2][1] + bh[2][1]));
            hA1 = (1.0f - z1) * n1 + z1 * hA1;
            float r2 = fsig(xB[0].x + biB[0][0] + acc[0][2] + bh[0][0]);
            float z2 = fsig(xB[1].x + biB[1][0] + acc[1][2] + bh[1][0]);
            float n2 = ftanh(xB[2].x + biB[2][0] + r2 * (acc[2][2] + bh[2][0]));
            hB0 = (1.0f - z2) * n2 + z2 * hB0;
            float r3 = fsig(xB[0].y + biB[0][1] + acc[0][3] + bh[0][1]);
            float z3 = fsig(xB[1].y + biB[1][1] + acc[1][3] + bh[1][1]);
            float n3 = ftanh(xB[2].y + biB[2][1] + r3 * (acc[2][3] + bh[2][1]));
            hB1 = (1.0f - z3) * n3 + z3 * hB1;
        }

        float2 oA = {hA0, hA1}, oB = {hB0, hB1};
        wr_h(hnxt, rA, hA0, hA1);
        wr_h(hnxt, rB, hB0, hB1);

        if (t == T_STEPS - 1) {
            *(float2*)&out[((size_t)t * B_SZ + rA) * H_DIM + jc] = oA;
            *(float2*)&out[((size_t)t * B_SZ + rB) * H_DIM + jc] = oB;
            if (wh) {
                *(float2*)&out[(size_t)M_TOT * H_DIM + (size_t)rA * H_DIM + jc] = oA;
                *(float2*)&out[(size_t)M_TOT * H_DIM + (size_t)rB * H_DIM + jc] = oB;
            }
        } else {
            bar_arrive();
            *(float2*)&out[((size_t)t * B_SZ + rA) * H_DIM + jc] = oA;
            *(float2*)&out[((size_t)t * B_SZ + rB) * H_DIM + jc] = oB;
            const float* gxn = g_gx + (size_t)(t + 1) * B_SZ * G3;
            #pragma unroll
            for (int g = 0; g < 3; g++) {
                xA[g] = *(const float2*)&gxn[(size_t)rA * G3 + g * 1024 + jc];
                xB[g] = *(const float2*)&gxn[(size_t)rB * G3 + g * 1024 + jc];
            }
            bar_wait(tgt);
            tgt += NBLK;
        }
    }
}

// ---------------- launch ------------------------------------------------------
extern "C" void kernel_launch(void* const* d_in, const int* in_sizes, int n_in,
                              void* d_out, int out_size) {
    const float* seq  = (const float*)d_in[0];
    const float* word = (const float*)d_in[1];
    const float* h0   = (const float*)d_in[2];
    const float* wih  = (const float*)d_in[3];
    const float* whh  = (const float*)d_in[4];
    const float* bih  = (const float*)d_in[5];
    const float* bhh  = (const float*)d_in[6];
    float* out = (float*)d_out;
    (void)in_sizes; (void)n_in;

    cudaFuncSetAttribute(k_gx_mma, cudaFuncAttributeMaxDynamicSharedMemorySize, GXS_SMEM);
    cudaFuncSetAttribute(k_gru_persist, cudaFuncAttributeMaxDynamicSharedMemorySize, PERS_SMEM);

    const int hidden_ok = (out_size >= T_STEPS * B_SZ * H_DIM + B_SZ * H_DIM) ? 1 : 0;

    k_cvt_whh<<<(G3 * H_DIM + 255) / 256, 256>>>(whh);
    k_cvt_wih<<<(G3 * KSEQ + 255) / 256, 256>>>(wih);
    k_xh<<<(int)(((size_t)M_TOT * KSEQ / 4 + 255) / 256), 256>>>(seq);
    k_word<<<B_SZ, 256>>>(word, wih);

    k_gx_mma<<<dim3(G3 / 128, M_TOT / 128), 256, GXS_SMEM>>>();

    k_gru_persist<<<NBLK, 256, PERS_SMEM>>>(h0, bih, bhh, out, hidden_ok);
}